// round 2
// baseline (speedup 1.0000x reference)
#include <cuda_runtime.h>

#define BS_ 2048
#define H_ 14
#define W_ 14
#define A_ 5
#define NC_ 2
#define G_ 30
#define CELLS_ (H_ * W_)      // 196
#define NBOX_ (A_ * CELLS_)   // 980
#define NCH_ (A_ * 7)         // 35

// Per-image loss scratch (no allocations allowed in kernel_launch).
__device__ float g_img_loss[BS_];

__global__ __launch_bounds__(256) void v2loss_img_kernel(
    const float* __restrict__ pred,
    const float* __restrict__ lab,
    const float* __restrict__ anchors,
    const int* __restrict__ seen_p)
{
    const int b = blockIdx.x;
    const int tid = threadIdx.x;
    const int nthr = blockDim.x;

    __shared__ float s_obj[CELLS_];
    __shared__ int s_cell[G_];
    __shared__ int s_nT;
    // Truth boxes in corner form for the IoU loop: (x1, y1, x2, y2) + area
    __shared__ float4 s_tbox[G_];
    __shared__ float s_tarea[G_];
    // Per-truth regression targets & metadata
    __shared__ float s_tc0[G_], s_tc1[G_], s_tc2[G_], s_tc3[G_];
    __shared__ float s_wgt[G_], s_cv1[G_], s_cv2[G_];
    // Match table: per cell, matched anchor id (or -1) and truth index
    __shared__ signed char s_matchA[CELLS_];
    __shared__ short s_matchG[CELLS_];
    __shared__ float s_abw[A_], s_abh[A_];
    __shared__ float s_part[8];

    const float* labb  = lab  + (size_t)b * 7 * CELLS_;
    const float* predb = pred + (size_t)b * NCH_ * CELLS_;

    if (tid < A_) {
        const float down = 512.0f / 14.0f;
        s_abw[tid] = anchors[tid * 2 + 0] / down / (float)W_;
        s_abh[tid] = anchors[tid * 2 + 1] / down / (float)H_;
    }
    for (int c = tid; c < CELLS_; c += nthr) {
        s_obj[c] = labb[c];          // channel 0 = objectness mask
        s_matchA[c] = -1;
    }
    __syncthreads();

    // Build truth list in ascending flat-cell order.
    // This matches lax.top_k's stable ordering over the {0,1} obj map.
    if (tid == 0) {
        int n = 0;
        for (int c = 0; c < CELLS_ && n < G_; ++c)
            if (s_obj[c] > 0.0f) s_cell[n++] = c;
        s_nT = n;
    }
    __syncthreads();
    const int nT = s_nT;

    if (tid < nT) {
        const int cell = s_cell[tid];
        const int r = cell / W_, c = cell % W_;
        const float tx = labb[3 * CELLS_ + cell];
        const float ty = labb[4 * CELLS_ + cell];
        const float tw = labb[5 * CELLS_ + cell];
        const float th = labb[6 * CELLS_ + cell];
        const float gx = (tx + (float)c) / (float)W_;
        const float gy = (ty + (float)r) / (float)H_;

        // argmax over anchors of intersection ratio (first-wins on ties)
        float best = -1e30f; int aid = 0;
        #pragma unroll
        for (int a = 0; a < A_; ++a) {
            const float aw = s_abw[a], ah = s_abh[a];
            const float ia = fminf(tw, aw) * fminf(th, ah);
            const float ratio = ia / (tw * th + aw * ah - ia);
            if (ratio > best) { best = ratio; aid = a; }
        }

        const float gxW = gx * (float)W_;
        const int wi = (int)gxW;
        const float fx = gxW - (float)wi;
        const float gyH = gy * (float)H_;
        const int hj = (int)gyH;
        const float fy = gyH - (float)hj;

        float4 tb;
        tb.x = gx - 0.5f * tw;
        tb.y = gy - 0.5f * th;
        tb.z = gx + 0.5f * tw;
        tb.w = gy + 0.5f * th;
        s_tbox[tid] = tb;
        s_tarea[tid] = tw * th;

        s_tc0[tid] = fx;
        s_tc1[tid] = fy;
        s_tc2[tid] = logf(tw / s_abw[aid]);
        s_tc3[tid] = logf(th / s_abh[aid]);
        s_wgt[tid] = 2.0f - fx * fy;

        const int mcell = hj * W_ + wi;
        s_matchA[mcell] = (signed char)aid;
        s_matchG[mcell] = (short)tid;
        s_cv1[tid] = labb[1 * CELLS_ + mcell];
        s_cv2[tid] = labb[2 * CELLS_ + mcell];
    }
    __syncthreads();

    const bool use_prior = (*seen_p) < 12800;
    float lsum = 0.0f;

    for (int i = tid; i < NBOX_; i += nthr) {
        const int a = i / CELLS_;
        const int cell = i - a * CELLS_;
        const int hh = cell / W_, ww = cell - hh * W_;
        const int base = a * 7 * CELLS_ + cell;

        const float pobj = predb[base + 0 * CELLS_];
        const float px   = predb[base + 3 * CELLS_];
        const float py   = predb[base + 4 * CELLS_];
        const float pw   = predb[base + 5 * CELLS_];
        const float ph   = predb[base + 6 * CELLS_];

        const float sx = 1.0f / (1.0f + expf(-px));
        const float sy = 1.0f / (1.0f + expf(-py));
        const float bx = (sx + (float)ww) / (float)W_;
        const float by = (sy + (float)hh) / (float)H_;
        const float bw = expf(pw) * s_abw[a];
        const float bh = expf(ph) * s_abh[a];

        const float bx1 = bx - 0.5f * bw, bx2 = bx + 0.5f * bw;
        const float by1 = by - 0.5f * bh, by2 = by + 0.5f * bh;
        const float area = bw * bh;

        const int mA = s_matchA[cell];
        const int mG = (mA == (signed char)a) ? (int)s_matchG[cell] : -1;

        float maxiou = 0.0f;
        float iou_sel = 0.0f;
        for (int g = 0; g < nT; ++g) {
            const float4 tb = s_tbox[g];
            const float xi1 = fmaxf(bx1, tb.x);
            const float yi1 = fmaxf(by1, tb.y);
            const float xi2 = fminf(bx2, tb.z);
            const float yi2 = fminf(by2, tb.w);
            const float iw = fmaxf(xi2 - xi1, 0.0f);
            const float ih = fmaxf(yi2 - yi1, 0.0f);
            const float inter = iw * ih;
            const float uni = area + s_tarea[g] - inter;
            const float iou = fmaxf(inter / uni, 0.0f);
            maxiou = fmaxf(maxiou, iou);
            if (g == mG) iou_sel = iou;
        }

        if (mG >= 0) {
            // matched box: coord + obj residuals, plus class loss
            const float w = s_wgt[mG];
            const float d0 = w * (sx - s_tc0[mG]);
            const float d1 = w * (sy - s_tc1[mG]);
            const float d2 = w * (pw - s_tc2[mG]);
            const float d3 = w * (ph - s_tc3[mG]);
            const float objl = 5.0f * (pobj - iou_sel);
            const float pc1 = predb[base + 1 * CELLS_];
            const float pc2 = predb[base + 2 * CELLS_];
            const float c1 = pc1 - s_cv1[mG];
            const float c2 = pc2 - s_cv2[mG];
            lsum += d0 * d0 + d1 * d1 + d2 * d2 + d3 * d3
                  + objl * objl + c1 * c1 + c2 * c2;
        } else {
            const float noobj = (maxiou <= 0.6f) ? 0.5f * pobj : 0.0f;
            float t = noobj * noobj;
            if (use_prior) {
                const float p0 = 0.01f * (sx - 0.5f);
                const float p1 = 0.01f * (sy - 0.5f);
                const float p2 = 0.01f * pw;
                const float p3 = 0.01f * ph;
                t += p0 * p0 + p1 * p1 + p2 * p2 + p3 * p3;
            }
            lsum += t;
        }
    }

    // block reduction
    float v = lsum;
    #pragma unroll
    for (int o = 16; o; o >>= 1) v += __shfl_down_sync(0xFFFFFFFFu, v, o);
    if ((tid & 31) == 0) s_part[tid >> 5] = v;
    __syncthreads();
    if (tid == 0) {
        float x = 0.0f;
        const int nw = (nthr + 31) >> 5;
        for (int wrp = 0; wrp < nw; ++wrp) x += s_part[wrp];
        g_img_loss[b] = (nT > 0) ? x : 0.0f;
    }
}

__global__ __launch_bounds__(256) void v2loss_reduce_kernel(float* __restrict__ out)
{
    const int tid = threadIdx.x;
    double s = 0.0;
    for (int i = tid; i < BS_; i += 256) s += (double)g_img_loss[i];
    #pragma unroll
    for (int o = 16; o; o >>= 1) s += __shfl_down_sync(0xFFFFFFFFu, s, o);
    __shared__ double sp[8];
    if ((tid & 31) == 0) sp[tid >> 5] = s;
    __syncthreads();
    if (tid == 0) {
        double t = 0.0;
        #pragma unroll
        for (int i = 0; i < 8; ++i) t += sp[i];
        out[0] = (float)(t / (double)BS_);
    }
}

extern "C" void kernel_launch(void* const* d_in, const int* in_sizes, int n_in,
                              void* d_out, int out_size)
{
    const float* pred    = (const float*)d_in[0];
    const float* label   = (const float*)d_in[1];
    const float* anchors = (const float*)d_in[2];
    const int*   seen    = (const int*)d_in[3];
    float* out = (float*)d_out;

    v2loss_img_kernel<<<BS_, 256>>>(pred, label, anchors, seen);
    v2loss_reduce_kernel<<<1, 256>>>(out);
}

// round 4
// speedup vs baseline: 2.9083x; 2.9083x over previous
#include <cuda_runtime.h>

#define BS_ 2048
#define H_ 14
#define W_ 14
#define A_ 5
#define NC_ 2
#define G_ 30
#define CELLS_ (H_ * W_)      // 196
#define NBOX_ (A_ * CELLS_)   // 980
#define NCH_ (A_ * 7)         // 35
#define NBPT 4                // boxes per thread (256 thr * 4 >= 980)

__device__ float g_img_loss[BS_];

__global__ __launch_bounds__(256) void v2loss_img_kernel(
    const float* __restrict__ pred,
    const float* __restrict__ lab,
    const float* __restrict__ anchors,
    const int* __restrict__ seen_p)
{
    const int b = blockIdx.x;
    const int tid = threadIdx.x;

    __shared__ int s_cell[G_];
    __shared__ int s_nT;
    __shared__ float4 s_tbox[G_];      // truth corners (x1,y1,x2,y2)
    __shared__ float s_t06[G_];        // 0.6 * truth area
    __shared__ float s_tarea[G_];
    __shared__ float s_tc0[G_], s_tc1[G_], s_tc2[G_], s_tc3[G_];
    __shared__ float s_wgt[G_], s_cv1[G_], s_cv2[G_];
    __shared__ signed char s_matchA[CELLS_];
    __shared__ short s_matchG[CELLS_];
    __shared__ float s_abw[A_], s_abh[A_];
    __shared__ int s_wcnt[8];
    __shared__ float s_part[8];

    const float* labb  = lab  + (size_t)b * 7 * CELLS_;
    const float* predb = pred + (size_t)b * NCH_ * CELLS_;

    if (tid < A_) {
        const float down = 512.0f / 14.0f;
        s_abw[tid] = anchors[tid * 2 + 0] / down / (float)W_;
        s_abh[tid] = anchors[tid * 2 + 1] / down / (float)H_;
    }
    if (tid < CELLS_) s_matchA[tid] = -1;

    // ---- Parallel ordered truth-list build (ballot prefix over cells) ----
    const int lane = tid & 31, wid = tid >> 5;
    const int flag = (tid < CELLS_) ? (labb[tid] > 0.0f) : 0;
    const unsigned bal = __ballot_sync(0xFFFFFFFFu, flag);
    if (lane == 0) s_wcnt[wid] = __popc(bal);
    __syncthreads();
    if (flag) {
        int off = 0;
        #pragma unroll
        for (int w2 = 0; w2 < 8; ++w2) off += (w2 < wid) ? s_wcnt[w2] : 0;
        const int pos = off + __popc(bal & ((1u << lane) - 1u));
        if (pos < G_) s_cell[pos] = tid;
    }
    if (tid == 0) {
        int t = 0;
        #pragma unroll
        for (int w2 = 0; w2 < 8; ++w2) t += s_wcnt[w2];
        s_nT = (t < G_) ? t : G_;
    }
    __syncthreads();
    const int nT = s_nT;

    // ---- Per-truth setup ----
    if (tid < nT) {
        const int cell = s_cell[tid];
        const int r = cell / W_, c = cell % W_;
        const float tx = labb[3 * CELLS_ + cell];
        const float ty = labb[4 * CELLS_ + cell];
        const float tw = labb[5 * CELLS_ + cell];
        const float th = labb[6 * CELLS_ + cell];
        const float gx = (tx + (float)c) / (float)W_;
        const float gy = (ty + (float)r) / (float)H_;

        float best = -1e30f; int aid = 0;
        #pragma unroll
        for (int a = 0; a < A_; ++a) {
            const float aw = s_abw[a], ah = s_abh[a];
            const float ia = fminf(tw, aw) * fminf(th, ah);
            const float ratio = ia / (tw * th + aw * ah - ia);
            if (ratio > best) { best = ratio; aid = a; }
        }

        const float gxW = gx * (float)W_;
        const int wi = (int)gxW;
        const float fx = gxW - (float)wi;
        const float gyH = gy * (float)H_;
        const int hj = (int)gyH;
        const float fy = gyH - (float)hj;

        float4 tb;
        tb.x = gx - 0.5f * tw;
        tb.y = gy - 0.5f * th;
        tb.z = gx + 0.5f * tw;
        tb.w = gy + 0.5f * th;
        s_tbox[tid] = tb;
        const float ta = tw * th;
        s_tarea[tid] = ta;
        s_t06[tid] = 0.6f * ta;

        s_tc0[tid] = fx;
        s_tc1[tid] = fy;
        s_tc2[tid] = logf(tw / s_abw[aid]);
        s_tc3[tid] = logf(th / s_abh[aid]);
        s_wgt[tid] = 2.0f - fx * fy;

        const int mcell = hj * W_ + wi;
        s_matchA[mcell] = (signed char)aid;
        s_matchG[mcell] = (short)tid;
        s_cv1[tid] = labb[1 * CELLS_ + mcell];
        s_cv2[tid] = labb[2 * CELLS_ + mcell];
    }
    __syncthreads();

    // ---- Per-box setup: geometry into registers ----
    float bx1[NBPT], by1[NBPT], bx2[NBPT], by2[NBPT];
    float areaR[NBPT], mAcc[NBPT];
    float sxR[NBPT], syR[NBPT], pwR[NBPT], phR[NBPT], poR[NBPT];

    #pragma unroll
    for (int k = 0; k < NBPT; ++k) {
        const int i = tid + k * 256;
        const bool vld = i < NBOX_;
        const int ii = vld ? i : 0;
        const int a = ii / CELLS_;
        const int cell = ii - a * CELLS_;
        const int hh = cell / W_, ww = cell - hh * W_;
        const int base = a * 7 * CELLS_ + cell;

        const float pobj = predb[base + 0 * CELLS_];
        const float px   = predb[base + 3 * CELLS_];
        const float py   = predb[base + 4 * CELLS_];
        const float pw   = predb[base + 5 * CELLS_];
        const float ph   = predb[base + 6 * CELLS_];

        const float sx = 1.0f / (1.0f + __expf(-px));
        const float sy = 1.0f / (1.0f + __expf(-py));
        const float bx = (sx + (float)ww) / (float)W_;
        const float by = (sy + (float)hh) / (float)H_;
        const float bw = __expf(pw) * s_abw[a];
        const float bh = __expf(ph) * s_abh[a];

        sxR[k] = sx; syR[k] = sy; pwR[k] = pw; phR[k] = ph; poR[k] = pobj;
        areaR[k] = bw * bh;
        bx1[k] = vld ? (bx - 0.5f * bw) :  1e30f;
        by1[k] = vld ? (by - 0.5f * bh) :  1e30f;
        bx2[k] = vld ? (bx + 0.5f * bw) : -1e30f;
        by2[k] = vld ? (by + 0.5f * bh) : -1e30f;
        mAcc[k] = -1e30f;
    }

    // ---- Hot loop: max over g of (1.6*inter - 0.6*tarea), division-free ----
    #pragma unroll 3
    for (int g = 0; g < nT; ++g) {
        const float4 tb = s_tbox[g];
        const float t06 = s_t06[g];
        #pragma unroll
        for (int k = 0; k < NBPT; ++k) {
            const float xi1 = fmaxf(bx1[k], tb.x);
            const float yi1 = fmaxf(by1[k], tb.y);
            const float xi2 = fminf(bx2[k], tb.z);
            const float yi2 = fminf(by2[k], tb.w);
            const float iw = fmaxf(xi2 - xi1, 0.0f);
            const float ih = fmaxf(yi2 - yi1, 0.0f);
            const float inter = iw * ih;
            mAcc[k] = fmaxf(mAcc[k], fmaf(1.6f, inter, -t06));
        }
    }

    // ---- Epilogue ----
    const bool use_prior = (*seen_p) < 12800;
    float lsum = 0.0f;

    #pragma unroll
    for (int k = 0; k < NBPT; ++k) {
        const int i = tid + k * 256;
        if (i >= NBOX_) continue;
        const int a = i / CELLS_;
        const int cell = i - a * CELLS_;

        const int mG = (s_matchA[cell] == (signed char)a) ? (int)s_matchG[cell] : -1;

        if (mG >= 0) {
            // matched box: exact iou for obj residual (one precise division)
            const float4 tb = s_tbox[mG];
            const float xi1 = fmaxf(bx1[k], tb.x);
            const float yi1 = fmaxf(by1[k], tb.y);
            const float xi2 = fminf(bx2[k], tb.z);
            const float yi2 = fminf(by2[k], tb.w);
            const float inter = fmaxf(xi2 - xi1, 0.0f) * fmaxf(yi2 - yi1, 0.0f);
            const float uni = areaR[k] + s_tarea[mG] - inter;
            const float iou = fmaxf(inter / uni, 0.0f);

            const float w = s_wgt[mG];
            const float d0 = w * (sxR[k] - s_tc0[mG]);
            const float d1 = w * (syR[k] - s_tc1[mG]);
            const float d2 = w * (pwR[k] - s_tc2[mG]);
            const float d3 = w * (phR[k] - s_tc3[mG]);
            const float objl = 5.0f * (poR[k] - iou);
            const int base = a * 7 * CELLS_ + cell;
            const float c1 = predb[base + 1 * CELLS_] - s_cv1[mG];
            const float c2 = predb[base + 2 * CELLS_] - s_cv2[mG];
            lsum += d0 * d0 + d1 * d1 + d2 * d2 + d3 * d3
                  + objl * objl + c1 * c1 + c2 * c2;
        } else {
            // maxiou <= 0.6  <=>  max(1.6*inter - 0.6*tarea) <= 0.6*area
            const float noobj = (mAcc[k] <= 0.6f * areaR[k]) ? 0.5f * poR[k] : 0.0f;
            float t = noobj * noobj;
            if (use_prior) {
                const float p0 = 0.01f * (sxR[k] - 0.5f);
                const float p1 = 0.01f * (syR[k] - 0.5f);
                const float p2 = 0.01f * pwR[k];
                const float p3 = 0.01f * phR[k];
                t += p0 * p0 + p1 * p1 + p2 * p2 + p3 * p3;
            }
            lsum += t;
        }
    }

    // ---- Block reduction ----
    float v = lsum;
    #pragma unroll
    for (int o = 16; o; o >>= 1) v += __shfl_down_sync(0xFFFFFFFFu, v, o);
    if ((tid & 31) == 0) s_part[tid >> 5] = v;
    __syncthreads();
    if (tid == 0) {
        float x = 0.0f;
        #pragma unroll
        for (int wrp = 0; wrp < 8; ++wrp) x += s_part[wrp];
        g_img_loss[b] = (nT > 0) ? x : 0.0f;
    }
}

__global__ __launch_bounds__(1024) void v2loss_reduce_kernel(float* __restrict__ out)
{
    const int tid = threadIdx.x;
    double s = 0.0;
    #pragma unroll
    for (int k = 0; k < 2; ++k) s += (double)g_img_loss[tid + k * 1024];
    #pragma unroll
    for (int o = 16; o; o >>= 1) s += __shfl_down_sync(0xFFFFFFFFu, s, o);
    __shared__ double sp[32];
    if ((tid & 31) == 0) sp[tid >> 5] = s;
    __syncthreads();
    if (tid == 0) {
        double t = 0.0;
        #pragma unroll
        for (int i = 0; i < 32; ++i) t += sp[i];
        out[0] = (float)(t / (double)BS_);
    }
}

extern "C" void kernel_launch(void* const* d_in, const int* in_sizes, int n_in,
                              void* d_out, int out_size)
{
    const float* pred    = (const float*)d_in[0];
    const float* label   = (const float*)d_in[1];
    const float* anchors = (const float*)d_in[2];
    const int*   seen    = (const int*)d_in[3];
    float* out = (float*)d_out;

    v2loss_img_kernel<<<BS_, 256>>>(pred, label, anchors, seen);
    v2loss_reduce_kernel<<<1, 1024>>>(out);
}

// round 6
// speedup vs baseline: 3.1386x; 1.0792x over previous
#include <cuda_runtime.h>

#define BS_ 2048
#define H_ 14
#define W_ 14
#define A_ 5
#define NC_ 2
#define G_ 30
#define CELLS_ (H_ * W_)      // 196
#define NBOX_ (A_ * CELLS_)   // 980
#define NCH_ (A_ * 7)         // 35
#define NBPT 4                // boxes per thread (256 thr * 4 >= 980)

__device__ float g_img_loss[BS_];
__device__ unsigned int g_sem = 0;

__global__ __launch_bounds__(256) void v2loss_fused_kernel(
    const float* __restrict__ pred,
    const float* __restrict__ lab,
    const float* __restrict__ anchors,
    const int* __restrict__ seen_p,
    float* __restrict__ out)
{
    const int b = blockIdx.x;
    const int tid = threadIdx.x;

    __shared__ int s_cell[G_];
    __shared__ int s_nT;
    __shared__ float4 s_tbox[G_];      // truth corners (x1,y1,x2,y2)
    __shared__ float s_thr[G_];        // 0.375 * truth area
    __shared__ float s_tarea[G_];
    __shared__ float s_tc0[G_], s_tc1[G_], s_tc2[G_], s_tc3[G_];
    __shared__ float s_wgt[G_], s_cv1[G_], s_cv2[G_];
    __shared__ signed char s_matchA[CELLS_];
    __shared__ short s_matchG[CELLS_];
    __shared__ float s_abw[A_], s_abh[A_];
    __shared__ int s_wcnt[8];
    __shared__ float s_part[8];
    __shared__ int s_islast;

    const float* labb  = lab  + (size_t)b * 7 * CELLS_;
    const float* predb = pred + (size_t)b * NCH_ * CELLS_;

    if (tid < A_) {
        const float down = 512.0f / 14.0f;
        s_abw[tid] = anchors[tid * 2 + 0] / down / (float)W_;
        s_abh[tid] = anchors[tid * 2 + 1] / down / (float)H_;
    }
    if (tid < CELLS_) s_matchA[tid] = -1;

    // ---- Parallel ordered truth-list build (ballot prefix over cells) ----
    const int lane = tid & 31, wid = tid >> 5;
    const int flag = (tid < CELLS_) ? (labb[tid] > 0.0f) : 0;
    const unsigned bal = __ballot_sync(0xFFFFFFFFu, flag);
    if (lane == 0) s_wcnt[wid] = __popc(bal);
    __syncthreads();
    if (flag) {
        int off = 0;
        #pragma unroll
        for (int w2 = 0; w2 < 8; ++w2) off += (w2 < wid) ? s_wcnt[w2] : 0;
        const int pos = off + __popc(bal & ((1u << lane) - 1u));
        if (pos < G_) s_cell[pos] = tid;
    }
    if (tid == 0) {
        int t = 0;
        #pragma unroll
        for (int w2 = 0; w2 < 8; ++w2) t += s_wcnt[w2];
        s_nT = (t < G_) ? t : G_;
    }
    __syncthreads();
    const int nT = s_nT;

    // ---- Per-truth setup ----
    if (tid < nT) {
        const int cell = s_cell[tid];
        const int r = cell / W_, c = cell % W_;
        const float tx = labb[3 * CELLS_ + cell];
        const float ty = labb[4 * CELLS_ + cell];
        const float tw = labb[5 * CELLS_ + cell];
        const float th = labb[6 * CELLS_ + cell];
        const float gx = (tx + (float)c) / (float)W_;
        const float gy = (ty + (float)r) / (float)H_;

        float best = -1e30f; int aid = 0;
        #pragma unroll
        for (int a = 0; a < A_; ++a) {
            const float aw = s_abw[a], ah = s_abh[a];
            const float ia = fminf(tw, aw) * fminf(th, ah);
            const float ratio = ia / (tw * th + aw * ah - ia);
            if (ratio > best) { best = ratio; aid = a; }
        }

        const float gxW = gx * (float)W_;
        const int wi = (int)gxW;
        const float fx = gxW - (float)wi;
        const float gyH = gy * (float)H_;
        const int hj = (int)gyH;
        const float fy = gyH - (float)hj;

        float4 tb;
        tb.x = gx - 0.5f * tw;
        tb.y = gy - 0.5f * th;
        tb.z = gx + 0.5f * tw;
        tb.w = gy + 0.5f * th;
        s_tbox[tid] = tb;
        const float ta = tw * th;
        s_tarea[tid] = ta;
        s_thr[tid] = 0.375f * ta;

        s_tc0[tid] = fx;
        s_tc1[tid] = fy;
        s_tc2[tid] = logf(tw / s_abw[aid]);
        s_tc3[tid] = logf(th / s_abh[aid]);
        s_wgt[tid] = 2.0f - fx * fy;

        const int mcell = hj * W_ + wi;
        s_matchA[mcell] = (signed char)aid;
        s_matchG[mcell] = (short)tid;
        s_cv1[tid] = labb[1 * CELLS_ + mcell];
        s_cv2[tid] = labb[2 * CELLS_ + mcell];
    }
    __syncthreads();

    // ---- Per-box setup: geometry into registers ----
    float bx1[NBPT], by1[NBPT], bx2[NBPT], by2[NBPT];
    float areaR[NBPT], mAcc[NBPT];
    float sxR[NBPT], syR[NBPT], pwR[NBPT], phR[NBPT], poR[NBPT];

    #pragma unroll
    for (int k = 0; k < NBPT; ++k) {
        const int i = tid + k * 256;
        const bool vld = i < NBOX_;
        const int ii = vld ? i : 0;
        const int a = ii / CELLS_;
        const int cell = ii - a * CELLS_;
        const int hh = cell / W_, ww = cell - hh * W_;
        const int base = a * 7 * CELLS_ + cell;

        const float pobj = predb[base + 0 * CELLS_];
        const float px   = predb[base + 3 * CELLS_];
        const float py   = predb[base + 4 * CELLS_];
        const float pw   = predb[base + 5 * CELLS_];
        const float ph   = predb[base + 6 * CELLS_];

        const float sx = 1.0f / (1.0f + __expf(-px));
        const float sy = 1.0f / (1.0f + __expf(-py));
        const float bx = (sx + (float)ww) / (float)W_;
        const float by = (sy + (float)hh) / (float)H_;
        const float bw = __expf(pw) * s_abw[a];
        const float bh = __expf(ph) * s_abh[a];

        sxR[k] = sx; syR[k] = sy; pwR[k] = pw; phR[k] = ph; poR[k] = pobj;
        areaR[k] = bw * bh;
        bx1[k] = vld ? (bx - 0.5f * bw) :  1e30f;
        by1[k] = vld ? (by - 0.5f * bh) :  1e30f;
        bx2[k] = vld ? (bx + 0.5f * bw) : -1e30f;
        by2[k] = vld ? (by + 0.5f * bh) : -1e30f;
        mAcc[k] = -1e30f;
    }

    // ---- Hot loop: mAcc = max_g( dxc*dy - 0.375*tarea_g ), division-free.
    // maxiou > 0.6  <=>  exists g: inter > 0.375*(area + tarea)
    //               <=>  mAcc > 0.375*area.
    // dy is left unclamped: when dy < 0 the candidate only becomes more
    // negative than the true (-thr) value, which can never cross the
    // strictly positive threshold 0.375*area.
    #pragma unroll 5
    for (int g = 0; g < nT; ++g) {
        const float4 tb = s_tbox[g];
        const float thr = s_thr[g];
        #pragma unroll
        for (int k = 0; k < NBPT; ++k) {
            const float xi1 = fmaxf(bx1[k], tb.x);
            const float yi1 = fmaxf(by1[k], tb.y);
            const float xi2 = fminf(bx2[k], tb.z);
            const float yi2 = fminf(by2[k], tb.w);
            const float dxc = fmaxf(xi2 - xi1, 0.0f);
            const float dy  = yi2 - yi1;
            mAcc[k] = fmaxf(mAcc[k], fmaf(dxc, dy, -thr));
        }
    }

    // ---- Epilogue ----
    const bool use_prior = (*seen_p) < 12800;
    float lsum = 0.0f;

    #pragma unroll
    for (int k = 0; k < NBPT; ++k) {
        const int i = tid + k * 256;
        if (i >= NBOX_) continue;
        const int a = i / CELLS_;
        const int cell = i - a * CELLS_;

        const int mG = (s_matchA[cell] == (signed char)a) ? (int)s_matchG[cell] : -1;

        if (mG >= 0) {
            // matched box: exact iou for obj residual (one precise division)
            const float4 tb = s_tbox[mG];
            const float xi1 = fmaxf(bx1[k], tb.x);
            const float yi1 = fmaxf(by1[k], tb.y);
            const float xi2 = fminf(bx2[k], tb.z);
            const float yi2 = fminf(by2[k], tb.w);
            const float inter = fmaxf(xi2 - xi1, 0.0f) * fmaxf(yi2 - yi1, 0.0f);
            const float uni = areaR[k] + s_tarea[mG] - inter;
            const float iou = fmaxf(inter / uni, 0.0f);

            const float w = s_wgt[mG];
            const float d0 = w * (sxR[k] - s_tc0[mG]);
            const float d1 = w * (syR[k] - s_tc1[mG]);
            const float d2 = w * (pwR[k] - s_tc2[mG]);
            const float d3 = w * (phR[k] - s_tc3[mG]);
            const float objl = 5.0f * (poR[k] - iou);
            const int base = a * 7 * CELLS_ + cell;
            const float c1 = predb[base + 1 * CELLS_] - s_cv1[mG];
            const float c2 = predb[base + 2 * CELLS_] - s_cv2[mG];
            lsum += d0 * d0 + d1 * d1 + d2 * d2 + d3 * d3
                  + objl * objl + c1 * c1 + c2 * c2;
        } else {
            const float noobj = (mAcc[k] <= 0.375f * areaR[k]) ? 0.5f * poR[k] : 0.0f;
            float t = noobj * noobj;
            if (use_prior) {
                const float p0 = 0.01f * (sxR[k] - 0.5f);
                const float p1 = 0.01f * (syR[k] - 0.5f);
                const float p2 = 0.01f * pwR[k];
                const float p3 = 0.01f * phR[k];
                t += p0 * p0 + p1 * p1 + p2 * p2 + p3 * p3;
            }
            lsum += t;
        }
    }

    // ---- Block reduction into g_img_loss[b] ----
    float v = lsum;
    #pragma unroll
    for (int o = 16; o; o >>= 1) v += __shfl_down_sync(0xFFFFFFFFu, v, o);
    if ((tid & 31) == 0) s_part[tid >> 5] = v;
    __syncthreads();
    if (tid == 0) {
        float x = 0.0f;
        #pragma unroll
        for (int wrp = 0; wrp < 8; ++wrp) x += s_part[wrp];
        g_img_loss[b] = (nT > 0) ? x : 0.0f;
        __threadfence();
        const unsigned old = atomicAdd(&g_sem, 1u);
        s_islast = (old == (unsigned)(gridDim.x - 1));
        if (s_islast) g_sem = 0;   // reset for next graph replay
    }
    __syncthreads();

    // ---- Last block: deterministic fixed-order final reduction ----
    if (s_islast) {
        __threadfence();
        __shared__ double sp[8];
        double s = 0.0;
        #pragma unroll
        for (int k = 0; k < BS_ / 256; ++k)
            s += (double)g_img_loss[tid + k * 256];
        #pragma unroll
        for (int o = 16; o; o >>= 1) s += __shfl_down_sync(0xFFFFFFFFu, s, o);
        if ((tid & 31) == 0) sp[tid >> 5] = s;
        __syncthreads();
        if (tid == 0) {
            double t = 0.0;
            #pragma unroll
            for (int i = 0; i < 8; ++i) t += sp[i];
            out[0] = (float)(t / (double)BS_);
        }
    }
}

extern "C" void kernel_launch(void* const* d_in, const int* in_sizes, int n_in,
                              void* d_out, int out_size)
{
    const float* pred    = (const float*)d_in[0];
    const float* label   = (const float*)d_in[1];
    const float* anchors = (const float*)d_in[2];
    const int*   seen    = (const int*)d_in[3];
    float* out = (float*)d_out;

    v2loss_fused_kernel<<<BS_, 256>>>(pred, label, anchors, seen, out);
}

// round 9
// speedup vs baseline: 3.2978x; 1.0507x over previous
#include <cuda_runtime.h>

#define BS_ 2048
#define H_ 14
#define W_ 14
#define A_ 5
#define NC_ 2
#define G_ 30
#define CELLS_ (H_ * W_)      // 196
#define NBOX_ (A_ * CELLS_)   // 980
#define NCH_ (A_ * 7)         // 35
#define NBPT 4                // boxes per thread (256 thr * 4 >= 980)

__device__ float g_img_loss[BS_];
__device__ unsigned int g_sem = 0;

__global__ __launch_bounds__(256, 5) void v2loss_fused_kernel(
    const float* __restrict__ pred,
    const float* __restrict__ lab,
    const float* __restrict__ anchors,
    const int* __restrict__ seen_p,
    float* __restrict__ out)
{
    const int b = blockIdx.x;
    const int tid = threadIdx.x;

    __shared__ int s_cell[G_];
    __shared__ int s_nT;
    __shared__ float4 s_tbox[G_];      // truth corners (x1,y1,x2,y2)
    __shared__ float s_thr[G_];        // 0.375 * truth area
    __shared__ float s_tarea[G_];
    __shared__ float s_tc0[G_], s_tc1[G_], s_tc2[G_], s_tc3[G_];
    __shared__ float s_wgt[G_], s_cv1[G_], s_cv2[G_];
    __shared__ signed char s_matchA[CELLS_];
    __shared__ short s_matchG[CELLS_];
    __shared__ float s_abw[A_], s_abh[A_];
    __shared__ int s_wcnt[8];
    __shared__ float s_part[8];
    __shared__ int s_islast;

    const float* labb  = lab  + (size_t)b * 7 * CELLS_;
    const float* predb = pred + (size_t)b * NCH_ * CELLS_;

    if (tid < A_) {
        const float down = 512.0f / 14.0f;
        s_abw[tid] = anchors[tid * 2 + 0] / down / (float)W_;
        s_abh[tid] = anchors[tid * 2 + 1] / down / (float)H_;
    }
    if (tid < CELLS_) s_matchA[tid] = -1;

    // ---- Parallel ordered truth-list build (ballot prefix over cells) ----
    const int lane = tid & 31, wid = tid >> 5;
    const int flag = (tid < CELLS_) ? (labb[tid] > 0.0f) : 0;
    const unsigned bal = __ballot_sync(0xFFFFFFFFu, flag);
    if (lane == 0) s_wcnt[wid] = __popc(bal);
    __syncthreads();
    if (flag) {
        int off = 0;
        #pragma unroll
        for (int w2 = 0; w2 < 8; ++w2) off += (w2 < wid) ? s_wcnt[w2] : 0;
        const int pos = off + __popc(bal & ((1u << lane) - 1u));
        if (pos < G_) s_cell[pos] = tid;
    }
    if (tid == 0) {
        int t = 0;
        #pragma unroll
        for (int w2 = 0; w2 < 8; ++w2) t += s_wcnt[w2];
        s_nT = (t < G_) ? t : G_;
    }
    __syncthreads();
    const int nT = s_nT;

    // ---- Per-truth setup ----
    if (tid < nT) {
        const int cell = s_cell[tid];
        const int r = cell / W_, c = cell % W_;
        const float tx = labb[3 * CELLS_ + cell];
        const float ty = labb[4 * CELLS_ + cell];
        const float tw = labb[5 * CELLS_ + cell];
        const float th = labb[6 * CELLS_ + cell];
        const float gx = (tx + (float)c) / (float)W_;
        const float gy = (ty + (float)r) / (float)H_;

        float best = -1e30f; int aid = 0;
        #pragma unroll
        for (int a = 0; a < A_; ++a) {
            const float aw = s_abw[a], ah = s_abh[a];
            const float ia = fminf(tw, aw) * fminf(th, ah);
            const float ratio = ia / (tw * th + aw * ah - ia);
            if (ratio > best) { best = ratio; aid = a; }
        }

        const float gxW = gx * (float)W_;
        const int wi = (int)gxW;
        const float fx = gxW - (float)wi;
        const float gyH = gy * (float)H_;
        const int hj = (int)gyH;
        const float fy = gyH - (float)hj;

        float4 tb;
        tb.x = gx - 0.5f * tw;
        tb.y = gy - 0.5f * th;
        tb.z = gx + 0.5f * tw;
        tb.w = gy + 0.5f * th;
        s_tbox[tid] = tb;
        const float ta = tw * th;
        s_tarea[tid] = ta;
        s_thr[tid] = 0.375f * ta;

        s_tc0[tid] = fx;
        s_tc1[tid] = fy;
        s_tc2[tid] = logf(tw / s_abw[aid]);
        s_tc3[tid] = logf(th / s_abh[aid]);
        s_wgt[tid] = 2.0f - fx * fy;

        const int mcell = hj * W_ + wi;
        s_matchA[mcell] = (signed char)aid;
        s_matchG[mcell] = (short)tid;
        s_cv1[tid] = labb[1 * CELLS_ + mcell];
        s_cv2[tid] = labb[2 * CELLS_ + mcell];
    }
    __syncthreads();

    // ---- Per-box setup: only geometry + pobj stay in registers ----
    float bx1[NBPT], by1[NBPT], bx2[NBPT], by2[NBPT];
    float mAcc[NBPT], poR[NBPT];

    #pragma unroll
    for (int k = 0; k < NBPT; ++k) {
        const int i = tid + k * 256;
        const bool vld = i < NBOX_;
        const int ii = vld ? i : 0;
        const int a = ii / CELLS_;
        const int cell = ii - a * CELLS_;
        const int hh = cell / W_, ww = cell - hh * W_;
        const int base = a * 7 * CELLS_ + cell;

        const float pobj = predb[base + 0 * CELLS_];
        const float px   = predb[base + 3 * CELLS_];
        const float py   = predb[base + 4 * CELLS_];
        const float pw   = predb[base + 5 * CELLS_];
        const float ph   = predb[base + 6 * CELLS_];

        const float sx = 1.0f / (1.0f + __expf(-px));
        const float sy = 1.0f / (1.0f + __expf(-py));
        const float bx = (sx + (float)ww) / (float)W_;
        const float by = (sy + (float)hh) / (float)H_;
        const float bw = __expf(pw) * s_abw[a];
        const float bh = __expf(ph) * s_abh[a];

        poR[k] = pobj;
        bx1[k] = vld ? (bx - 0.5f * bw) :  1e30f;
        by1[k] = vld ? (by - 0.5f * bh) :  1e30f;
        bx2[k] = vld ? (bx + 0.5f * bw) : -1e30f;
        by2[k] = vld ? (by + 0.5f * bh) : -1e30f;
        mAcc[k] = -1e30f;
    }

    // ---- Hot loop: mAcc = max_g( dxc*dy - 0.375*tarea_g ), division-free.
    // maxiou > 0.6  <=>  exists g: inter > 0.375*(area + tarea)
    //               <=>  mAcc > 0.375*area.
    // dy left unclamped: dy < 0 only drives the candidate more negative,
    // which can never cross the strictly positive threshold 0.375*area.
    #pragma unroll 5
    for (int g = 0; g < nT; ++g) {
        const float4 tb = s_tbox[g];
        const float thr = s_thr[g];
        #pragma unroll
        for (int k = 0; k < NBPT; ++k) {
            const float xi1 = fmaxf(bx1[k], tb.x);
            const float yi1 = fmaxf(by1[k], tb.y);
            const float xi2 = fminf(bx2[k], tb.z);
            const float yi2 = fminf(by2[k], tb.w);
            const float dxc = fmaxf(xi2 - xi1, 0.0f);
            const float dy  = yi2 - yi1;
            mAcc[k] = fmaxf(mAcc[k], fmaf(dxc, dy, -thr));
        }
    }

    // ---- Epilogue: recompute per-box transforms (pred is L1-resident) ----
    const bool use_prior = (*seen_p) < 12800;
    float lsum = 0.0f;

    #pragma unroll
    for (int k = 0; k < NBPT; ++k) {
        const int i = tid + k * 256;
        if (i >= NBOX_) continue;
        const int a = i / CELLS_;
        const int cell = i - a * CELLS_;
        const int base = a * 7 * CELLS_ + cell;

        const float px = predb[base + 3 * CELLS_];
        const float py = predb[base + 4 * CELLS_];
        const float pw = predb[base + 5 * CELLS_];
        const float ph = predb[base + 6 * CELLS_];
        const float sx = 1.0f / (1.0f + __expf(-px));
        const float sy = 1.0f / (1.0f + __expf(-py));
        const float bw = __expf(pw) * s_abw[a];
        const float bh = __expf(ph) * s_abh[a];
        const float area = bw * bh;

        const int mG = (s_matchA[cell] == (signed char)a) ? (int)s_matchG[cell] : -1;

        if (mG >= 0) {
            // matched box: exact iou for obj residual (one precise division)
            const float4 tb = s_tbox[mG];
            const float xi1 = fmaxf(bx1[k], tb.x);
            const float yi1 = fmaxf(by1[k], tb.y);
            const float xi2 = fminf(bx2[k], tb.z);
            const float yi2 = fminf(by2[k], tb.w);
            const float inter = fmaxf(xi2 - xi1, 0.0f) * fmaxf(yi2 - yi1, 0.0f);
            const float uni = area + s_tarea[mG] - inter;
            const float iou = fmaxf(inter / uni, 0.0f);

            const float w = s_wgt[mG];
            const float d0 = w * (sx - s_tc0[mG]);
            const float d1 = w * (sy - s_tc1[mG]);
            const float d2 = w * (pw - s_tc2[mG]);
            const float d3 = w * (ph - s_tc3[mG]);
            const float objl = 5.0f * (poR[k] - iou);
            const float c1 = predb[base + 1 * CELLS_] - s_cv1[mG];
            const float c2 = predb[base + 2 * CELLS_] - s_cv2[mG];
            lsum += d0 * d0 + d1 * d1 + d2 * d2 + d3 * d3
                  + objl * objl + c1 * c1 + c2 * c2;
        } else {
            const float noobj = (mAcc[k] <= 0.375f * area) ? 0.5f * poR[k] : 0.0f;
            float t = noobj * noobj;
            if (use_prior) {
                const float p0 = 0.01f * (sx - 0.5f);
                const float p1 = 0.01f * (sy - 0.5f);
                const float p2 = 0.01f * pw;
                const float p3 = 0.01f * ph;
                t += p0 * p0 + p1 * p1 + p2 * p2 + p3 * p3;
            }
            lsum += t;
        }
    }

    // ---- Block reduction into g_img_loss[b] ----
    float v = lsum;
    #pragma unroll
    for (int o = 16; o; o >>= 1) v += __shfl_down_sync(0xFFFFFFFFu, v, o);
    if ((tid & 31) == 0) s_part[tid >> 5] = v;
    __syncthreads();
    if (tid == 0) {
        float x = 0.0f;
        #pragma unroll
        for (int wrp = 0; wrp < 8; ++wrp) x += s_part[wrp];
        g_img_loss[b] = (nT > 0) ? x : 0.0f;
        __threadfence();
        const unsigned old = atomicAdd(&g_sem, 1u);
        s_islast = (old == (unsigned)(gridDim.x - 1));
        if (s_islast) g_sem = 0;   // reset for next graph replay
    }
    __syncthreads();

    // ---- Last block: deterministic fixed-order final reduction ----
    if (s_islast) {
        __threadfence();
        __shared__ double sp[8];
        double s = 0.0;
        #pragma unroll
        for (int k = 0; k < BS_ / 256; ++k)
            s += (double)g_img_loss[tid + k * 256];
        #pragma unroll
        for (int o = 16; o; o >>= 1) s += __shfl_down_sync(0xFFFFFFFFu, s, o);
        if ((tid & 31) == 0) sp[tid >> 5] = s;
        __syncthreads();
        if (tid == 0) {
            double t = 0.0;
            #pragma unroll
            for (int i = 0; i < 8; ++i) t += sp[i];
            out[0] = (float)(t / (double)BS_);
        }
    }
}

extern "C" void kernel_launch(void* const* d_in, const int* in_sizes, int n_in,
                              void* d_out, int out_size)
{
    const float* pred    = (const float*)d_in[0];
    const float* label   = (const float*)d_in[1];
    const float* anchors = (const float*)d_in[2];
    const int*   seen    = (const int*)d_in[3];
    float* out = (float*)d_out;

    v2loss_fused_kernel<<<BS_, 256>>>(pred, label, anchors, seen, out);
}

// round 14
// speedup vs baseline: 3.6807x; 1.1161x over previous
#include <cuda_runtime.h>

#define BS_ 2048
#define H_ 14
#define W_ 14
#define A_ 5
#define NC_ 2
#define G_ 30
#define CELLS_ (H_ * W_)      // 196
#define NBOX_ (A_ * CELLS_)   // 980
#define NCH_ (A_ * 7)         // 35
#define NBPT 4                // boxes per thread (256 thr * 4 >= 980)

__device__ float g_img_loss[BS_];
__device__ unsigned int g_sem = 0;

__global__ __launch_bounds__(256, 5) void v2loss_fused_kernel(
    const float* __restrict__ pred,
    const float* __restrict__ lab,
    const float* __restrict__ anchors,
    const int* __restrict__ seen_p,
    float* __restrict__ out)
{
    const int b = blockIdx.x;
    const int tid = threadIdx.x;

    __shared__ int s_cell[G_];
    __shared__ int s_nT;
    __shared__ float4 s_tbox[G_];      // truth corners (x1,y1,x2,y2)
    __shared__ float s_thr[G_];        // 0.375 * truth area
    __shared__ float s_tarea[G_];
    __shared__ float s_tc0[G_], s_tc1[G_], s_tc2[G_], s_tc3[G_];
    __shared__ float s_wgt[G_], s_cv1[G_], s_cv2[G_];
    __shared__ signed char s_matchA[CELLS_];
    __shared__ short s_matchG[CELLS_];
    __shared__ float s_abw[A_], s_abh[A_];
    __shared__ int s_wcnt[8];
    __shared__ float s_part[8];
    __shared__ int s_islast;

    const float* labb  = lab  + (size_t)b * 7 * CELLS_;
    const float* predb = pred + (size_t)b * NCH_ * CELLS_;

    if (tid < A_) {
        const float down = 512.0f / 14.0f;
        s_abw[tid] = anchors[tid * 2 + 0] / down / (float)W_;
        s_abh[tid] = anchors[tid * 2 + 1] / down / (float)H_;
    }
    if (tid < CELLS_) s_matchA[tid] = -1;

    // ---- Parallel ordered truth-list build (ballot prefix over cells) ----
    const int lane = tid & 31, wid = tid >> 5;
    const int flag = (tid < CELLS_) ? (labb[tid] > 0.0f) : 0;
    const unsigned bal = __ballot_sync(0xFFFFFFFFu, flag);
    if (lane == 0) s_wcnt[wid] = __popc(bal);
    __syncthreads();
    if (flag) {
        int off = 0;
        #pragma unroll
        for (int w2 = 0; w2 < 8; ++w2) off += (w2 < wid) ? s_wcnt[w2] : 0;
        const int pos = off + __popc(bal & ((1u << lane) - 1u));
        if (pos < G_) s_cell[pos] = tid;
    }
    if (tid == 0) {
        int t = 0;
        #pragma unroll
        for (int w2 = 0; w2 < 8; ++w2) t += s_wcnt[w2];
        s_nT = (t < G_) ? t : G_;
    }
    __syncthreads();
    const int nT = s_nT;

    // ---- Per-truth setup ----
    if (tid < nT) {
        const int cell = s_cell[tid];
        const int r = cell / W_, c = cell % W_;
        const float tx = labb[3 * CELLS_ + cell];
        const float ty = labb[4 * CELLS_ + cell];
        const float tw = labb[5 * CELLS_ + cell];
        const float th = labb[6 * CELLS_ + cell];
        const float gx = (tx + (float)c) / (float)W_;
        const float gy = (ty + (float)r) / (float)H_;

        float best = -1e30f; int aid = 0;
        #pragma unroll
        for (int a = 0; a < A_; ++a) {
            const float aw = s_abw[a], ah = s_abh[a];
            const float ia = fminf(tw, aw) * fminf(th, ah);
            const float ratio = ia / (tw * th + aw * ah - ia);
            if (ratio > best) { best = ratio; aid = a; }
        }

        const float gxW = gx * (float)W_;
        const int wi = (int)gxW;
        const float fx = gxW - (float)wi;
        const float gyH = gy * (float)H_;
        const int hj = (int)gyH;
        const float fy = gyH - (float)hj;

        float4 tb;
        tb.x = gx - 0.5f * tw;
        tb.y = gy - 0.5f * th;
        tb.z = gx + 0.5f * tw;
        tb.w = gy + 0.5f * th;
        s_tbox[tid] = tb;
        const float ta = tw * th;
        s_tarea[tid] = ta;
        s_thr[tid] = 0.375f * ta;

        s_tc0[tid] = fx;
        s_tc1[tid] = fy;
        s_tc2[tid] = logf(tw / s_abw[aid]);
        s_tc3[tid] = logf(th / s_abh[aid]);
        s_wgt[tid] = 2.0f - fx * fy;

        const int mcell = hj * W_ + wi;
        s_matchA[mcell] = (signed char)aid;
        s_matchG[mcell] = (short)tid;
        s_cv1[tid] = labb[1 * CELLS_ + mcell];
        s_cv2[tid] = labb[2 * CELLS_ + mcell];
    }
    __syncthreads();

    const bool use_prior = (*seen_p) < 12800;

    // ---- Per-box phase: transforms + matched residuals + prior terms,
    //      all while channels are live in registers. Only the noobj
    //      boolean is deferred (needs mAcc from the hot loop).
    float bx1[NBPT], by1[NBPT], bx2[NBPT], by2[NBPT];
    float mAcc[NBPT], thrR[NBPT], qR[NBPT];
    float lsum = 0.0f;

    #pragma unroll
    for (int k = 0; k < NBPT; ++k) {
        const int i = tid + k * 256;
        const bool vld = i < NBOX_;
        const int ii = vld ? i : 0;
        const int a = ii / CELLS_;
        const int cell = ii - a * CELLS_;
        const int hh = cell / W_, ww = cell - hh * W_;
        const int base = a * 7 * CELLS_ + cell;

        const float pobj = predb[base + 0 * CELLS_];
        const float px   = predb[base + 3 * CELLS_];
        const float py   = predb[base + 4 * CELLS_];
        const float pw   = predb[base + 5 * CELLS_];
        const float ph   = predb[base + 6 * CELLS_];

        const float sx = __fdividef(1.0f, 1.0f + __expf(-px));
        const float sy = __fdividef(1.0f, 1.0f + __expf(-py));
        const float bx = __fdividef(sx + (float)ww, (float)W_);
        const float by = __fdividef(sy + (float)hh, (float)H_);
        const float bw = __expf(pw) * s_abw[a];
        const float bh = __expf(ph) * s_abh[a];
        const float area = bw * bh;

        const float gx1 = bx - 0.5f * bw, gx2 = bx + 0.5f * bw;
        const float gy1 = by - 0.5f * bh, gy2 = by + 0.5f * bh;
        bx1[k] = vld ? gx1 :  1e30f;
        by1[k] = vld ? gy1 :  1e30f;
        bx2[k] = vld ? gx2 : -1e30f;
        by2[k] = vld ? gy2 : -1e30f;
        mAcc[k] = -1e30f;

        const int mG = (vld && s_matchA[cell] == (signed char)a)
                       ? (int)s_matchG[cell] : -1;

        if (mG >= 0) {
            // matched: full residual now (exact iou, one precise division)
            const float4 tb = s_tbox[mG];
            const float xi1 = fmaxf(gx1, tb.x);
            const float yi1 = fmaxf(gy1, tb.y);
            const float xi2 = fminf(gx2, tb.z);
            const float yi2 = fminf(gy2, tb.w);
            const float inter = fmaxf(xi2 - xi1, 0.0f) * fmaxf(yi2 - yi1, 0.0f);
            const float uni = area + s_tarea[mG] - inter;
            const float iou = fmaxf(inter / uni, 0.0f);

            const float w = s_wgt[mG];
            const float d0 = w * (sx - s_tc0[mG]);
            const float d1 = w * (sy - s_tc1[mG]);
            const float d2 = w * (pw - s_tc2[mG]);
            const float d3 = w * (ph - s_tc3[mG]);
            const float objl = 5.0f * (pobj - iou);
            const float c1 = predb[base + 1 * CELLS_] - s_cv1[mG];
            const float c2 = predb[base + 2 * CELLS_] - s_cv2[mG];
            lsum += d0 * d0 + d1 * d1 + d2 * d2 + d3 * d3
                  + objl * objl + c1 * c1 + c2 * c2;
            qR[k] = 0.0f;            // matched cells carry no noobj/prior
            thrR[k] = 0.0f;
        } else if (vld) {
            if (use_prior) {
                const float p0 = 0.01f * (sx - 0.5f);
                const float p1 = 0.01f * (sy - 0.5f);
                const float p2 = 0.01f * pw;
                const float p3 = 0.01f * ph;
                lsum += p0 * p0 + p1 * p1 + p2 * p2 + p3 * p3;
            }
            qR[k] = 0.25f * pobj * pobj;   // == (0.5*pobj)^2 bit-exactly
            thrR[k] = 0.375f * area;
        } else {
            qR[k] = 0.0f;
            thrR[k] = 0.0f;
        }
    }

    // ---- Hot loop: mAcc = max_g( dxc*dy - 0.375*tarea_g ), division-free.
    // maxiou > 0.6  <=>  exists g: inter > 0.375*(area + tarea)
    //               <=>  mAcc > 0.375*area (= thrR).
    // dy left unclamped: dy < 0 only drives the candidate more negative,
    // which can never cross the strictly positive threshold.
    #pragma unroll 5
    for (int g = 0; g < nT; ++g) {
        const float4 tb = s_tbox[g];
        const float thr = s_thr[g];
        #pragma unroll
        for (int k = 0; k < NBPT; ++k) {
            const float xi1 = fmaxf(bx1[k], tb.x);
            const float yi1 = fmaxf(by1[k], tb.y);
            const float xi2 = fminf(bx2[k], tb.z);
            const float yi2 = fminf(by2[k], tb.w);
            const float dxc = fmaxf(xi2 - xi1, 0.0f);
            const float dy  = yi2 - yi1;
            mAcc[k] = fmaxf(mAcc[k], fmaf(dxc, dy, -thr));
        }
    }

    // ---- Deferred noobj terms ----
    #pragma unroll
    for (int k = 0; k < NBPT; ++k)
        lsum += (mAcc[k] <= thrR[k]) ? qR[k] : 0.0f;

    // ---- Block reduction into g_img_loss[b] ----
    float v = lsum;
    #pragma unroll
    for (int o = 16; o; o >>= 1) v += __shfl_down_sync(0xFFFFFFFFu, v, o);
    if ((tid & 31) == 0) s_part[tid >> 5] = v;
    __syncthreads();
    if (tid == 0) {
        float x = 0.0f;
        #pragma unroll
        for (int wrp = 0; wrp < 8; ++wrp) x += s_part[wrp];
        g_img_loss[b] = (nT > 0) ? x : 0.0f;
        __threadfence();
        const unsigned old = atomicAdd(&g_sem, 1u);
        s_islast = (old == (unsigned)(gridDim.x - 1));
        if (s_islast) g_sem = 0;   // reset for next graph replay
    }
    __syncthreads();

    // ---- Last block: deterministic fixed-order final reduction ----
    if (s_islast) {
        __threadfence();
        __shared__ double sp[8];
        double s = 0.0;
        #pragma unroll
        for (int k = 0; k < BS_ / 256; ++k)
            s += (double)g_img_loss[tid + k * 256];
        #pragma unroll
        for (int o = 16; o; o >>= 1) s += __shfl_down_sync(0xFFFFFFFFu, s, o);
        if ((tid & 31) == 0) sp[tid >> 5] = s;
        __syncthreads();
        if (tid == 0) {
            double t = 0.0;
            #pragma unroll
            for (int i = 0; i < 8; ++i) t += sp[i];
            out[0] = (float)(t / (double)BS_);
        }
    }
}

extern "C" void kernel_launch(void* const* d_in, const int* in_sizes, int n_in,
                              void* d_out, int out_size)
{
    const float* pred    = (const float*)d_in[0];
    const float* label   = (const float*)d_in[1];
    const float* anchors = (const float*)d_in[2];
    const int*   seen    = (const int*)d_in[3];
    float* out = (float*)d_out;

    v2loss_fused_kernel<<<BS_, 256>>>(pred, label, anchors, seen, out);
}